// round 11
// baseline (speedup 1.0000x reference)
#include <cuda_runtime.h>
#include <math.h>

// ---------------------------------------------------------------------------
// Problem constants
// ---------------------------------------------------------------------------
#define BATCH   8
#define HH      128
#define WW2     128
#define DIM     180
#define NHEAD   6
#define HD      30
#define WS      16
#define SS      8
#define HIDDEN  360
#define NTOK    (BATCH * HH * WW2)          // 131072 rows
#define QKVC    (3 * DIM)                   // 540

// ---------------------------------------------------------------------------
// f32x2 packed math (Blackwell sm_103a)
// ---------------------------------------------------------------------------
#define PACK_F32X2(out, lo, hi) \
    asm("mov.b64 %0, {%1, %2};" : "=l"(out) : "f"(lo), "f"(hi))
#define UNPACK_F32X2(lo, hi, in) \
    asm("mov.b64 {%0, %1}, %2;" : "=f"(lo), "=f"(hi) : "l"(in))
#define FMA_F32X2(d, a, b, c) \
    asm("fma.rn.f32x2 %0, %1, %2, %3;" : "=l"(d) : "l"(a), "l"(b), "l"(c))

__device__ __forceinline__ float gelu_f(float v) {
    return 0.5f * v * (1.0f + erff(v * 0.70710678118654752440f));
}

// ---------------------------------------------------------------------------
// Scratch (device globals — no runtime allocation allowed)
// ---------------------------------------------------------------------------
__device__ float g_ln  [(size_t)NTOK * DIM];     //  94 MB  (LN output, reused)
__device__ float g_qkv [(size_t)NTOK * QKVC];    // 283 MB
__device__ float g_awin[(size_t)NTOK * DIM];     //  94 MB  (attn out, window layout)
__device__ float g_xres[(size_t)NTOK * DIM];     //  94 MB  (x + attn proj)
__device__ float g_y   [(size_t)NTOK * HIDDEN];  // 189 MB  (gelu(fc1))
__device__ float g_y2  [(size_t)NTOK * HIDDEN];  // 189 MB  (y + gelu(dwconv))

// ---------------------------------------------------------------------------
// LayerNorm: one warp per row of 180
// ---------------------------------------------------------------------------
__global__ void __launch_bounds__(256)
ln_kernel(const float* __restrict__ x, const float* __restrict__ w,
          const float* __restrict__ bb, float* __restrict__ out) {
    int lane = threadIdx.x & 31;
    int row  = blockIdx.x * 8 + (threadIdx.x >> 5);
    const float* xr = x + (size_t)row * DIM;

    float v[6];
    float s = 0.f;
#pragma unroll
    for (int i = 0; i < 6; i++) {
        int c = lane + i * 32;
        v[i] = (c < DIM) ? xr[c] : 0.f;
        s += v[i];
    }
#pragma unroll
    for (int o = 16; o; o >>= 1) s += __shfl_xor_sync(0xffffffffu, s, o);
    float mean = s * (1.0f / DIM);

    float vs = 0.f;
#pragma unroll
    for (int i = 0; i < 6; i++) {
        int c = lane + i * 32;
        if (c < DIM) { float d = v[i] - mean; vs += d * d; }
    }
#pragma unroll
    for (int o = 16; o; o >>= 1) vs += __shfl_xor_sync(0xffffffffu, vs, o);
    float rs = rsqrtf(vs * (1.0f / DIM) + 1e-5f);

    float* orow = out + (size_t)row * DIM;
#pragma unroll
    for (int i = 0; i < 6; i++) {
        int c = lane + i * 32;
        if (c < DIM) orow[c] = (v[i] - mean) * rs * w[c] + bb[c];
    }
}

// ---------------------------------------------------------------------------
// Generic tiled GEMM: C[M,N] = A[M,K] @ W[K,N] (+ epilogue)
// BM=BN=128, BK=20, 256 threads, 8x8 per thread, f32x2 FMA.
// EPI: 0=+bias  1=gelu(+bias)  2=window-scatter + residual x  3=+bias+res
// ---------------------------------------------------------------------------
template <int EPI>
__global__ void __launch_bounds__(256)
gemm_kernel(const float* __restrict__ A, const float* __restrict__ Wm,
            const float* __restrict__ bias, float* __restrict__ C,
            const float* __restrict__ res, int M, int N, int K) {
    __shared__ float sA[20][132];   // transposed A tile, padded (row 528B, 16B-aligned)
    __shared__ float sB[20][128];

    int tid = threadIdx.x;
    int tx = tid & 15, ty = tid >> 4;
    int m0 = blockIdx.y << 7, n0 = blockIdx.x << 7;

    unsigned long long acc2[8][4];
#pragma unroll
    for (int i = 0; i < 8; i++)
#pragma unroll
        for (int j = 0; j < 4; j++) acc2[i][j] = 0ull;

    for (int kb = 0; kb < K; kb += 20) {
#pragma unroll
        for (int i = 0; i < 10; i++) {
            int idx = tid + (i << 8);            // 0..2559
            int r = idx / 20, c = idx - r * 20;
            sA[c][r] = A[(size_t)(m0 + r) * K + kb + c];
            int rb = idx >> 7, cb = idx & 127;
            int col = n0 + cb;
            sB[rb][cb] = (col < N) ? Wm[(size_t)(kb + rb) * N + col] : 0.f;
        }
        __syncthreads();
#pragma unroll
        for (int kk = 0; kk < 20; kk++) {
            const float4* pa = reinterpret_cast<const float4*>(&sA[kk][ty << 3]);
            float4 a0 = pa[0], a1 = pa[1];
            const ulonglong2* pb = reinterpret_cast<const ulonglong2*>(&sB[kk][tx << 3]);
            ulonglong2 b0 = pb[0], b1 = pb[1];
            float av[8] = {a0.x, a0.y, a0.z, a0.w, a1.x, a1.y, a1.z, a1.w};
#pragma unroll
            for (int i = 0; i < 8; i++) {
                unsigned long long ap;
                PACK_F32X2(ap, av[i], av[i]);
                FMA_F32X2(acc2[i][0], ap, b0.x, acc2[i][0]);
                FMA_F32X2(acc2[i][1], ap, b0.y, acc2[i][1]);
                FMA_F32X2(acc2[i][2], ap, b1.x, acc2[i][2]);
                FMA_F32X2(acc2[i][3], ap, b1.y, acc2[i][3]);
            }
        }
        __syncthreads();
    }

    // ---- epilogue ----
#pragma unroll
    for (int i = 0; i < 8; i++) {
        int m = m0 + (ty << 3) + i;
        size_t obase;
        if (EPI == 2) {
            // m = b*16384 + win*256 + t  ->  scatter back through reverse shift
            int b  = m >> 14;
            int ri = m & 16383;
            int wi = ri >> 8;
            int t  = ri & 255;
            int hh = (((wi >> 3) << 4) + (t >> 4) + SS) & 127;
            int ww = (((wi & 7) << 4) + (t & 15) + SS) & 127;
            int drow = (b << 14) + (hh << 7) + ww;
            obase = (size_t)drow * DIM;
        } else {
            obase = (size_t)m * N;
        }
#pragma unroll
        for (int jp = 0; jp < 4; jp++) {
            float lo, hi;
            UNPACK_F32X2(lo, hi, acc2[i][jp]);
            float vals[2] = {lo, hi};
            int nbase = n0 + (tx << 3) + (jp << 1);
#pragma unroll
            for (int e = 0; e < 2; e++) {
                int nn = nbase + e;
                if (nn < N) {
                    float v = vals[e] + bias[nn];
                    if (EPI == 1) v = gelu_f(v);
                    if (EPI == 2) v += res[obase + nn];
                    if (EPI == 3) v += res[obase + nn];
                    C[obase + nn] = v;
                }
            }
        }
    }
}

// ---------------------------------------------------------------------------
// Fused shifted-window attention: one block per (window, head), 256 threads.
// Mask computed analytically from coordinates; rel-pos bias table in SMEM.
// Streaming softmax (scores are small; clamped at 60).
// ---------------------------------------------------------------------------
__global__ void __launch_bounds__(256)
attn_kernel(const float* __restrict__ qkv, const float* __restrict__ rpb,
            float* __restrict__ awin) {
    extern __shared__ float smem[];
    float* sk   = smem;                         // 256 * 32
    float* sv   = smem + 8192;                  // 256 * 32
    float* srpb = smem + 16384;                 // 961
    int*   sgrow = (int*)(smem + 16384 + 961);  // 256
    int*   scnt  = sgrow + 256;                 // 256

    int t   = threadIdx.x;
    int wgl = blockIdx.x;       // global window 0..511
    int hid = blockIdx.y;       // head 0..5
    int b  = wgl >> 6, wi = wgl & 63;
    int wy = wi >> 3,  wx = wi & 7;
    int li = t >> 4,   lj = t & 15;

    // rolled gather position (same mapping used for the output scatter)
    int gr = ((wy << 4) + li + SS) & 127;
    int gc = ((wx << 4) + lj + SS) & 127;
    int grow = (b << 14) + (gr << 7) + gc;

    // region id on the UNROLLED grid (Swin mask)
    int ur = (wy << 4) + li, uc = (wx << 4) + lj;
    int rh = (ur < 112) ? 0 : (ur < 120 ? 1 : 2);
    int rc = (uc < 112) ? 0 : (uc < 120 ? 1 : 2);
    int myCnt = rh * 3 + rc;

    sgrow[t] = grow;
    scnt[t]  = myCnt;
    sk[(t << 5) + 30] = 0.f; sk[(t << 5) + 31] = 0.f;
    sv[(t << 5) + 30] = 0.f; sv[(t << 5) + 31] = 0.f;
    for (int idx = t; idx < 961; idx += 256) srpb[idx] = rpb[idx * NHEAD + hid];
    __syncthreads();

    // cooperative, mostly-coalesced K/V fill
    for (int idx = t; idx < 256 * HD; idx += 256) {
        int t2 = idx / HD;
        int d  = idx - t2 * HD;
        int gb = sgrow[t2] * QKVC + hid * HD + d;
        sk[(t2 << 5) + d] = qkv[gb + DIM];
        sv[(t2 << 5) + d] = qkv[gb + 2 * DIM];
    }

    // per-thread query (pre-scaled), packed into f32x2 pairs
    unsigned long long q2[16];
    {
        float qv[32];
        int qb = grow * QKVC + hid * HD;
#pragma unroll
        for (int d = 0; d < HD; d++) qv[d] = qkv[qb + d] * 0.18257418583505536f;
        qv[30] = 0.f; qv[31] = 0.f;
#pragma unroll
        for (int i = 0; i < 16; i++) PACK_F32X2(q2[i], qv[2 * i], qv[2 * i + 1]);
    }
    __syncthreads();

    unsigned long long acc2[16];
#pragma unroll
    for (int i = 0; i < 16; i++) acc2[i] = 0ull;
    float l = 0.f;
    int base_t = (li + 15) * 31 + (lj + 15);

    for (int j = 0; j < 256; j++) {
        const ulonglong2* kp = reinterpret_cast<const ulonglong2*>(sk + (j << 5));
        unsigned long long sa = 0ull, sb = 0ull;
#pragma unroll
        for (int i = 0; i < 8; i++) {
            ulonglong2 kk = kp[i];
            FMA_F32X2(sa, q2[2 * i],     kk.x, sa);
            FMA_F32X2(sb, q2[2 * i + 1], kk.y, sb);
        }
        float a0, a1, b0, b1;
        UNPACK_F32X2(a0, a1, sa);
        UNPACK_F32X2(b0, b1, sb);
        float s = (a0 + b0) + (a1 + b1);

        int off = ((j >> 4) * 31) + (j & 15);
        s += srpb[base_t - off];
        s = (scnt[j] == myCnt) ? s : (s - 100.0f);
        float p = __expf(fminf(s, 60.0f));
        l += p;

        unsigned long long p2;
        PACK_F32X2(p2, p, p);
        const ulonglong2* vp = reinterpret_cast<const ulonglong2*>(sv + (j << 5));
#pragma unroll
        for (int i = 0; i < 8; i++) {
            ulonglong2 vv = vp[i];
            FMA_F32X2(acc2[2 * i],     p2, vv.x, acc2[2 * i]);
            FMA_F32X2(acc2[2 * i + 1], p2, vv.y, acc2[2 * i + 1]);
        }
    }

    float inv = 1.0f / l;
    float* orow = awin + ((size_t)(wgl << 8) + t) * DIM + hid * HD;
#pragma unroll
    for (int i = 0; i < 15; i++) {
        float lo, hi;
        UNPACK_F32X2(lo, hi, acc2[i]);
        orow[2 * i]     = lo * inv;
        orow[2 * i + 1] = hi * inv;
    }
}

// ---------------------------------------------------------------------------
// Depthwise 5x5 conv (channel-last), fused +bias, gelu, +y residual.
// One thread per channel; 8 output columns via register sliding window.
// ---------------------------------------------------------------------------
__global__ void __launch_bounds__(384)
conv_kernel(const float* __restrict__ y, const float* __restrict__ dw,
            const float* __restrict__ db, float* __restrict__ y2) {
    int ch = threadIdx.x;
    if (ch >= HIDDEN) return;
    int c0 = blockIdx.x << 3;
    int r  = blockIdx.y;
    int b  = blockIdx.z;

    float wreg[25];
#pragma unroll
    for (int k = 0; k < 25; k++) wreg[k] = dw[ch * 25 + k];

    float acc[8] = {0, 0, 0, 0, 0, 0, 0, 0};
    float center[8];
    const float* ybase = y + ((size_t)b << 14) * HIDDEN;

#pragma unroll
    for (int ky = 0; ky < 5; ky++) {
        int ry = r + ky - 2;
        bool rv = (ry >= 0) && (ry < HH);
        float v[12];
#pragma unroll
        for (int xx = 0; xx < 12; xx++) {
            int cx = c0 + xx - 2;
            bool cv = rv && (cx >= 0) && (cx < WW2);
            v[xx] = cv ? ybase[((size_t)(ry << 7) + cx) * HIDDEN + ch] : 0.f;
        }
        if (ky == 2) {
#pragma unroll
            for (int o = 0; o < 8; o++) center[o] = v[o + 2];
        }
#pragma unroll
        for (int o = 0; o < 8; o++)
#pragma unroll
            for (int kx = 0; kx < 5; kx++)
                acc[o] = fmaf(v[o + kx], wreg[ky * 5 + kx], acc[o]);
    }

    float bch = db[ch];
#pragma unroll
    for (int o = 0; o < 8; o++) {
        float g = gelu_f(acc[o] + bch);
        y2[(((size_t)b << 14) + (r << 7) + c0 + o) * HIDDEN + ch] = center[o] + g;
    }
}

// ---------------------------------------------------------------------------
// Launch
// ---------------------------------------------------------------------------
#define ATTN_SMEM ((16384 + 961 + 512) * 4)   // 71428 bytes

extern "C" void kernel_launch(void* const* d_in, const int* in_sizes, int n_in,
                              void* d_out, int out_size) {
    const float* x       = (const float*)d_in[0];
    const float* norm1_w = (const float*)d_in[3];
    const float* norm1_b = (const float*)d_in[4];
    const float* wqkv_w  = (const float*)d_in[5];
    const float* wqkv_b  = (const float*)d_in[6];
    const float* rpb     = (const float*)d_in[7];
    const float* proj_w  = (const float*)d_in[8];
    const float* proj_b  = (const float*)d_in[9];
    const float* norm2_w = (const float*)d_in[10];
    const float* norm2_b = (const float*)d_in[11];
    const float* fc1_w   = (const float*)d_in[12];
    const float* fc1_b   = (const float*)d_in[13];
    const float* dw_w    = (const float*)d_in[14];
    const float* dw_b    = (const float*)d_in[15];
    const float* fc2_w   = (const float*)d_in[16];
    const float* fc2_b   = (const float*)d_in[17];
    float* out = (float*)d_out;

    float *ln, *qkv, *awin, *xres, *y, *y2;
    cudaGetSymbolAddress((void**)&ln,   g_ln);
    cudaGetSymbolAddress((void**)&qkv,  g_qkv);
    cudaGetSymbolAddress((void**)&awin, g_awin);
    cudaGetSymbolAddress((void**)&xres, g_xres);
    cudaGetSymbolAddress((void**)&y,    g_y);
    cudaGetSymbolAddress((void**)&y2,   g_y2);

    cudaFuncSetAttribute(attn_kernel,
                         cudaFuncAttributeMaxDynamicSharedMemorySize, ATTN_SMEM);

    const int M = NTOK;

    // 1) LN1
    ln_kernel<<<M / 8, 256>>>(x, norm1_w, norm1_b, ln);
    // 2) QKV GEMM  (M x 180 @ 180 x 540) + bias
    gemm_kernel<0><<<dim3(5, M / 128), 256>>>(ln, wqkv_w, wqkv_b, qkv, nullptr,
                                              M, QKVC, DIM);
    // 3) windowed attention -> awin (window layout)
    attn_kernel<<<dim3(512, NHEAD), 256, ATTN_SMEM>>>(qkv, rpb, awin);
    // 4) proj GEMM + scatter(reverse shift) + residual x -> xres
    gemm_kernel<2><<<dim3(2, M / 128), 256>>>(awin, proj_w, proj_b, xres, x,
                                              M, DIM, DIM);
    // 5) LN2
    ln_kernel<<<M / 8, 256>>>(xres, norm2_w, norm2_b, ln);
    // 6) fc1 GEMM + gelu -> y
    gemm_kernel<1><<<dim3(3, M / 128), 256>>>(ln, fc1_w, fc1_b, y, nullptr,
                                              M, HIDDEN, DIM);
    // 7) depthwise conv + gelu + residual y -> y2
    conv_kernel<<<dim3(16, 128, 8), 384>>>(y, dw_w, dw_b, y2);
    // 8) fc2 GEMM + bias + residual xres -> out
    gemm_kernel<3><<<dim3(2, M / 128), 256>>>(y2, fc2_w, fc2_b, out, xres,
                                              M, DIM, HIDDEN);
}

// round 12
// speedup vs baseline: 1.0001x; 1.0001x over previous
#include <cuda_runtime.h>
#include <math.h>

// ---------------------------------------------------------------------------
// Problem constants
// ---------------------------------------------------------------------------
#define BATCH   8
#define HH      128
#define WW2     128
#define DIM     180
#define NHEAD   6
#define HD      30
#define WS      16
#define SS      8
#define HIDDEN  360
#define NTOK    (BATCH * HH * WW2)          // 131072 rows
#define QKVC    (3 * DIM)                   // 540

// ---------------------------------------------------------------------------
// f32x2 packed math (Blackwell sm_103a)
// ---------------------------------------------------------------------------
#define PACK_F32X2(out, lo, hi) \
    asm("mov.b64 %0, {%1, %2};" : "=l"(out) : "f"(lo), "f"(hi))
#define UNPACK_F32X2(lo, hi, in) \
    asm("mov.b64 {%0, %1}, %2;" : "=f"(lo), "=f"(hi) : "l"(in))
#define FMA_F32X2(d, a, b, c) \
    asm("fma.rn.f32x2 %0, %1, %2, %3;" : "=l"(d) : "l"(a), "l"(b), "l"(c))

__device__ __forceinline__ float gelu_f(float v) {
    return 0.5f * v * (1.0f + erff(v * 0.70710678118654752440f));
}

// ---------------------------------------------------------------------------
// Scratch (device globals — no runtime allocation allowed)
// ---------------------------------------------------------------------------
__device__ float g_ln  [(size_t)NTOK * DIM];     //  94 MB  (LN output, reused)
__device__ float g_qkv [(size_t)NTOK * QKVC];    // 283 MB
__device__ float g_awin[(size_t)NTOK * DIM];     //  94 MB  (attn out, window layout)
__device__ float g_xres[(size_t)NTOK * DIM];     //  94 MB  (x + attn proj)
__device__ float g_y   [(size_t)NTOK * HIDDEN];  // 189 MB  (gelu(fc1))
__device__ float g_y2  [(size_t)NTOK * HIDDEN];  // 189 MB  (y + gelu(dwconv))

// ---------------------------------------------------------------------------
// LayerNorm: one warp per row of 180
// ---------------------------------------------------------------------------
__global__ void __launch_bounds__(256)
ln_kernel(const float* __restrict__ x, const float* __restrict__ w,
          const float* __restrict__ bb, float* __restrict__ out) {
    int lane = threadIdx.x & 31;
    int row  = blockIdx.x * 8 + (threadIdx.x >> 5);
    const float* xr = x + (size_t)row * DIM;

    float v[6];
    float s = 0.f;
#pragma unroll
    for (int i = 0; i < 6; i++) {
        int c = lane + i * 32;
        v[i] = (c < DIM) ? xr[c] : 0.f;
        s += v[i];
    }
#pragma unroll
    for (int o = 16; o; o >>= 1) s += __shfl_xor_sync(0xffffffffu, s, o);
    float mean = s * (1.0f / DIM);

    float vs = 0.f;
#pragma unroll
    for (int i = 0; i < 6; i++) {
        int c = lane + i * 32;
        if (c < DIM) { float d = v[i] - mean; vs += d * d; }
    }
#pragma unroll
    for (int o = 16; o; o >>= 1) vs += __shfl_xor_sync(0xffffffffu, vs, o);
    float rs = rsqrtf(vs * (1.0f / DIM) + 1e-5f);

    float* orow = out + (size_t)row * DIM;
#pragma unroll
    for (int i = 0; i < 6; i++) {
        int c = lane + i * 32;
        if (c < DIM) orow[c] = (v[i] - mean) * rs * w[c] + bb[c];
    }
}

// ---------------------------------------------------------------------------
// Generic tiled GEMM: C[M,N] = A[M,K] @ W[K,N] (+ epilogue)
// BM=BN=128, BK=20, 256 threads, 8x8 per thread, f32x2 FMA.
// EPI: 0=+bias  1=gelu(+bias)  2=window-scatter + residual x  3=+bias+res
// ---------------------------------------------------------------------------
template <int EPI>
__global__ void __launch_bounds__(256)
gemm_kernel(const float* __restrict__ A, const float* __restrict__ Wm,
            const float* __restrict__ bias, float* __restrict__ C,
            const float* __restrict__ res, int M, int N, int K) {
    __shared__ float sA[20][132];   // transposed A tile, padded (row 528B, 16B-aligned)
    __shared__ float sB[20][128];

    int tid = threadIdx.x;
    int tx = tid & 15, ty = tid >> 4;
    int m0 = blockIdx.y << 7, n0 = blockIdx.x << 7;

    unsigned long long acc2[8][4];
#pragma unroll
    for (int i = 0; i < 8; i++)
#pragma unroll
        for (int j = 0; j < 4; j++) acc2[i][j] = 0ull;

    for (int kb = 0; kb < K; kb += 20) {
#pragma unroll
        for (int i = 0; i < 10; i++) {
            int idx = tid + (i << 8);            // 0..2559
            int r = idx / 20, c = idx - r * 20;
            sA[c][r] = A[(size_t)(m0 + r) * K + kb + c];
            int rb = idx >> 7, cb = idx & 127;
            int col = n0 + cb;
            sB[rb][cb] = (col < N) ? Wm[(size_t)(kb + rb) * N + col] : 0.f;
        }
        __syncthreads();
#pragma unroll
        for (int kk = 0; kk < 20; kk++) {
            const float4* pa = reinterpret_cast<const float4*>(&sA[kk][ty << 3]);
            float4 a0 = pa[0], a1 = pa[1];
            const ulonglong2* pb = reinterpret_cast<const ulonglong2*>(&sB[kk][tx << 3]);
            ulonglong2 b0 = pb[0], b1 = pb[1];
            float av[8] = {a0.x, a0.y, a0.z, a0.w, a1.x, a1.y, a1.z, a1.w};
#pragma unroll
            for (int i = 0; i < 8; i++) {
                unsigned long long ap;
                PACK_F32X2(ap, av[i], av[i]);
                FMA_F32X2(acc2[i][0], ap, b0.x, acc2[i][0]);
                FMA_F32X2(acc2[i][1], ap, b0.y, acc2[i][1]);
                FMA_F32X2(acc2[i][2], ap, b1.x, acc2[i][2]);
                FMA_F32X2(acc2[i][3], ap, b1.y, acc2[i][3]);
            }
        }
        __syncthreads();
    }

    // ---- epilogue ----
#pragma unroll
    for (int i = 0; i < 8; i++) {
        int m = m0 + (ty << 3) + i;
        size_t obase;
        if (EPI == 2) {
            // m = b*16384 + win*256 + t  ->  scatter back through reverse shift
            int b  = m >> 14;
            int ri = m & 16383;
            int wi = ri >> 8;
            int t  = ri & 255;
            int hh = (((wi >> 3) << 4) + (t >> 4) + SS) & 127;
            int ww = (((wi & 7) << 4) + (t & 15) + SS) & 127;
            int drow = (b << 14) + (hh << 7) + ww;
            obase = (size_t)drow * DIM;
        } else {
            obase = (size_t)m * N;
        }
#pragma unroll
        for (int jp = 0; jp < 4; jp++) {
            float lo, hi;
            UNPACK_F32X2(lo, hi, acc2[i][jp]);
            float vals[2] = {lo, hi};
            int nbase = n0 + (tx << 3) + (jp << 1);
#pragma unroll
            for (int e = 0; e < 2; e++) {
                int nn = nbase + e;
                if (nn < N) {
                    float v = vals[e] + bias[nn];
                    if (EPI == 1) v = gelu_f(v);
                    if (EPI == 2) v += res[obase + nn];
                    if (EPI == 3) v += res[obase + nn];
                    C[obase + nn] = v;
                }
            }
        }
    }
}

// ---------------------------------------------------------------------------
// Fused shifted-window attention: one block per (window, head), 256 threads.
// Mask computed analytically from coordinates; rel-pos bias table in SMEM.
// Streaming softmax (scores are small; clamped at 60).
// ---------------------------------------------------------------------------
__global__ void __launch_bounds__(256)
attn_kernel(const float* __restrict__ qkv, const float* __restrict__ rpb,
            float* __restrict__ awin) {
    extern __shared__ float smem[];
    float* sk   = smem;                         // 256 * 32
    float* sv   = smem + 8192;                  // 256 * 32
    float* srpb = smem + 16384;                 // 961
    int*   sgrow = (int*)(smem + 16384 + 961);  // 256
    int*   scnt  = sgrow + 256;                 // 256

    int t   = threadIdx.x;
    int wgl = blockIdx.x;       // global window 0..511
    int hid = blockIdx.y;       // head 0..5
    int b  = wgl >> 6, wi = wgl & 63;
    int wy = wi >> 3,  wx = wi & 7;
    int li = t >> 4,   lj = t & 15;

    // rolled gather position (same mapping used for the output scatter)
    int gr = ((wy << 4) + li + SS) & 127;
    int gc = ((wx << 4) + lj + SS) & 127;
    int grow = (b << 14) + (gr << 7) + gc;

    // region id on the UNROLLED grid (Swin mask)
    int ur = (wy << 4) + li, uc = (wx << 4) + lj;
    int rh = (ur < 112) ? 0 : (ur < 120 ? 1 : 2);
    int rc = (uc < 112) ? 0 : (uc < 120 ? 1 : 2);
    int myCnt = rh * 3 + rc;

    sgrow[t] = grow;
    scnt[t]  = myCnt;
    sk[(t << 5) + 30] = 0.f; sk[(t << 5) + 31] = 0.f;
    sv[(t << 5) + 30] = 0.f; sv[(t << 5) + 31] = 0.f;
    for (int idx = t; idx < 961; idx += 256) srpb[idx] = rpb[idx * NHEAD + hid];
    __syncthreads();

    // cooperative, mostly-coalesced K/V fill
    for (int idx = t; idx < 256 * HD; idx += 256) {
        int t2 = idx / HD;
        int d  = idx - t2 * HD;
        int gb = sgrow[t2] * QKVC + hid * HD + d;
        sk[(t2 << 5) + d] = qkv[gb + DIM];
        sv[(t2 << 5) + d] = qkv[gb + 2 * DIM];
    }

    // per-thread query (pre-scaled), packed into f32x2 pairs
    unsigned long long q2[16];
    {
        float qv[32];
        int qb = grow * QKVC + hid * HD;
#pragma unroll
        for (int d = 0; d < HD; d++) qv[d] = qkv[qb + d] * 0.18257418583505536f;
        qv[30] = 0.f; qv[31] = 0.f;
#pragma unroll
        for (int i = 0; i < 16; i++) PACK_F32X2(q2[i], qv[2 * i], qv[2 * i + 1]);
    }
    __syncthreads();

    unsigned long long acc2[16];
#pragma unroll
    for (int i = 0; i < 16; i++) acc2[i] = 0ull;
    float l = 0.f;
    int base_t = (li + 15) * 31 + (lj + 15);

    for (int j = 0; j < 256; j++) {
        const ulonglong2* kp = reinterpret_cast<const ulonglong2*>(sk + (j << 5));
        unsigned long long sa = 0ull, sb = 0ull;
#pragma unroll
        for (int i = 0; i < 8; i++) {
            ulonglong2 kk = kp[i];
            FMA_F32X2(sa, q2[2 * i],     kk.x, sa);
            FMA_F32X2(sb, q2[2 * i + 1], kk.y, sb);
        }
        float a0, a1, b0, b1;
        UNPACK_F32X2(a0, a1, sa);
        UNPACK_F32X2(b0, b1, sb);
        float s = (a0 + b0) + (a1 + b1);

        int off = ((j >> 4) * 31) + (j & 15);
        s += srpb[base_t - off];
        s = (scnt[j] == myCnt) ? s : (s - 100.0f);
        float p = __expf(fminf(s, 60.0f));
        l += p;

        unsigned long long p2;
        PACK_F32X2(p2, p, p);
        const ulonglong2* vp = reinterpret_cast<const ulonglong2*>(sv + (j << 5));
#pragma unroll
        for (int i = 0; i < 8; i++) {
            ulonglong2 vv = vp[i];
            FMA_F32X2(acc2[2 * i],     p2, vv.x, acc2[2 * i]);
            FMA_F32X2(acc2[2 * i + 1], p2, vv.y, acc2[2 * i + 1]);
        }
    }

    float inv = 1.0f / l;
    float* orow = awin + ((size_t)(wgl << 8) + t) * DIM + hid * HD;
#pragma unroll
    for (int i = 0; i < 15; i++) {
        float lo, hi;
        UNPACK_F32X2(lo, hi, acc2[i]);
        orow[2 * i]     = lo * inv;
        orow[2 * i + 1] = hi * inv;
    }
}

// ---------------------------------------------------------------------------
// Depthwise 5x5 conv (channel-last), fused +bias, gelu, +y residual.
// One thread per channel; 8 output columns via register sliding window.
// ---------------------------------------------------------------------------
__global__ void __launch_bounds__(384)
conv_kernel(const float* __restrict__ y, const float* __restrict__ dw,
            const float* __restrict__ db, float* __restrict__ y2) {
    int ch = threadIdx.x;
    if (ch >= HIDDEN) return;
    int c0 = blockIdx.x << 3;
    int r  = blockIdx.y;
    int b  = blockIdx.z;

    float wreg[25];
#pragma unroll
    for (int k = 0; k < 25; k++) wreg[k] = dw[ch * 25 + k];

    float acc[8] = {0, 0, 0, 0, 0, 0, 0, 0};
    float center[8];
    const float* ybase = y + ((size_t)b << 14) * HIDDEN;

#pragma unroll
    for (int ky = 0; ky < 5; ky++) {
        int ry = r + ky - 2;
        bool rv = (ry >= 0) && (ry < HH);
        float v[12];
#pragma unroll
        for (int xx = 0; xx < 12; xx++) {
            int cx = c0 + xx - 2;
            bool cv = rv && (cx >= 0) && (cx < WW2);
            v[xx] = cv ? ybase[((size_t)(ry << 7) + cx) * HIDDEN + ch] : 0.f;
        }
        if (ky == 2) {
#pragma unroll
            for (int o = 0; o < 8; o++) center[o] = v[o + 2];
        }
#pragma unroll
        for (int o = 0; o < 8; o++)
#pragma unroll
            for (int kx = 0; kx < 5; kx++)
                acc[o] = fmaf(v[o + kx], wreg[ky * 5 + kx], acc[o]);
    }

    float bch = db[ch];
#pragma unroll
    for (int o = 0; o < 8; o++) {
        float g = gelu_f(acc[o] + bch);
        y2[(((size_t)b << 14) + (r << 7) + c0 + o) * HIDDEN + ch] = center[o] + g;
    }
}

// ---------------------------------------------------------------------------
// Launch
// ---------------------------------------------------------------------------
#define ATTN_SMEM ((16384 + 961 + 512) * 4)   // 71428 bytes

extern "C" void kernel_launch(void* const* d_in, const int* in_sizes, int n_in,
                              void* d_out, int out_size) {
    const float* x       = (const float*)d_in[0];
    const float* norm1_w = (const float*)d_in[3];
    const float* norm1_b = (const float*)d_in[4];
    const float* wqkv_w  = (const float*)d_in[5];
    const float* wqkv_b  = (const float*)d_in[6];
    const float* rpb     = (const float*)d_in[7];
    const float* proj_w  = (const float*)d_in[8];
    const float* proj_b  = (const float*)d_in[9];
    const float* norm2_w = (const float*)d_in[10];
    const float* norm2_b = (const float*)d_in[11];
    const float* fc1_w   = (const float*)d_in[12];
    const float* fc1_b   = (const float*)d_in[13];
    const float* dw_w    = (const float*)d_in[14];
    const float* dw_b    = (const float*)d_in[15];
    const float* fc2_w   = (const float*)d_in[16];
    const float* fc2_b   = (const float*)d_in[17];
    float* out = (float*)d_out;

    float *ln, *qkv, *awin, *xres, *y, *y2;
    cudaGetSymbolAddress((void**)&ln,   g_ln);
    cudaGetSymbolAddress((void**)&qkv,  g_qkv);
    cudaGetSymbolAddress((void**)&awin, g_awin);
    cudaGetSymbolAddress((void**)&xres, g_xres);
    cudaGetSymbolAddress((void**)&y,    g_y);
    cudaGetSymbolAddress((void**)&y2,   g_y2);

    cudaFuncSetAttribute(attn_kernel,
                         cudaFuncAttributeMaxDynamicSharedMemorySize, ATTN_SMEM);

    const int M = NTOK;

    // 1) LN1
    ln_kernel<<<M / 8, 256>>>(x, norm1_w, norm1_b, ln);
    // 2) QKV GEMM  (M x 180 @ 180 x 540) + bias
    gemm_kernel<0><<<dim3(5, M / 128), 256>>>(ln, wqkv_w, wqkv_b, qkv, nullptr,
                                              M, QKVC, DIM);
    // 3) windowed attention -> awin (window layout)
    attn_kernel<<<dim3(512, NHEAD), 256, ATTN_SMEM>>>(qkv, rpb, awin);
    // 4) proj GEMM + scatter(reverse shift) + residual x -> xres
    gemm_kernel<2><<<dim3(2, M / 128), 256>>>(awin, proj_w, proj_b, xres, x,
                                              M, DIM, DIM);
    // 5) LN2
    ln_kernel<<<M / 8, 256>>>(xres, norm2_w, norm2_b, ln);
    // 6) fc1 GEMM + gelu -> y
    gemm_kernel<1><<<dim3(3, M / 128), 256>>>(ln, fc1_w, fc1_b, y, nullptr,
                                              M, HIDDEN, DIM);
    // 7) depthwise conv + gelu + residual y -> y2
    conv_kernel<<<dim3(16, 128, 8), 384>>>(y, dw_w, dw_b, y2);
    // 8) fc2 GEMM + bias + residual xres -> out
    gemm_kernel<3><<<dim3(2, M / 128), 256>>>(y2, fc2_w, fc2_b, out, xres,
                                              M, DIM, HIDDEN);
}

// round 13
// speedup vs baseline: 1.0007x; 1.0006x over previous
#include <cuda_runtime.h>
#include <math.h>

// ---------------------------------------------------------------------------
// Problem constants
// ---------------------------------------------------------------------------
#define BATCH   8
#define HH      128
#define WW2     128
#define DIM     180
#define NHEAD   6
#define HD      30
#define WS      16
#define SS      8
#define HIDDEN  360
#define NTOK    (BATCH * HH * WW2)          // 131072 rows
#define QKVC    (3 * DIM)                   // 540

// ---------------------------------------------------------------------------
// f32x2 packed math (Blackwell sm_103a)
// ---------------------------------------------------------------------------
#define PACK_F32X2(out, lo, hi) \
    asm("mov.b64 %0, {%1, %2};" : "=l"(out) : "f"(lo), "f"(hi))
#define UNPACK_F32X2(lo, hi, in) \
    asm("mov.b64 {%0, %1}, %2;" : "=f"(lo), "=f"(hi) : "l"(in))
#define FMA_F32X2(d, a, b, c) \
    asm("fma.rn.f32x2 %0, %1, %2, %3;" : "=l"(d) : "l"(a), "l"(b), "l"(c))

__device__ __forceinline__ float gelu_f(float v) {
    return 0.5f * v * (1.0f + erff(v * 0.70710678118654752440f));
}

// ---------------------------------------------------------------------------
// Scratch (device globals — no runtime allocation allowed)
// ---------------------------------------------------------------------------
__device__ float g_ln  [(size_t)NTOK * DIM];     //  94 MB  (LN output, reused)
__device__ float g_qkv [(size_t)NTOK * QKVC];    // 283 MB
__device__ float g_awin[(size_t)NTOK * DIM];     //  94 MB  (attn out, window layout)
__device__ float g_xres[(size_t)NTOK * DIM];     //  94 MB  (x + attn proj)
__device__ float g_y   [(size_t)NTOK * HIDDEN];  // 189 MB  (gelu(fc1))
__device__ float g_y2  [(size_t)NTOK * HIDDEN];  // 189 MB  (y + gelu(dwconv))

// ---------------------------------------------------------------------------
// LayerNorm: one warp per row of 180
// ---------------------------------------------------------------------------
__global__ void __launch_bounds__(256)
ln_kernel(const float* __restrict__ x, const float* __restrict__ w,
          const float* __restrict__ bb, float* __restrict__ out) {
    int lane = threadIdx.x & 31;
    int row  = blockIdx.x * 8 + (threadIdx.x >> 5);
    const float* xr = x + (size_t)row * DIM;

    float v[6];
    float s = 0.f;
#pragma unroll
    for (int i = 0; i < 6; i++) {
        int c = lane + i * 32;
        v[i] = (c < DIM) ? xr[c] : 0.f;
        s += v[i];
    }
#pragma unroll
    for (int o = 16; o; o >>= 1) s += __shfl_xor_sync(0xffffffffu, s, o);
    float mean = s * (1.0f / DIM);

    float vs = 0.f;
#pragma unroll
    for (int i = 0; i < 6; i++) {
        int c = lane + i * 32;
        if (c < DIM) { float d = v[i] - mean; vs += d * d; }
    }
#pragma unroll
    for (int o = 16; o; o >>= 1) vs += __shfl_xor_sync(0xffffffffu, vs, o);
    float rs = rsqrtf(vs * (1.0f / DIM) + 1e-5f);

    float* orow = out + (size_t)row * DIM;
#pragma unroll
    for (int i = 0; i < 6; i++) {
        int c = lane + i * 32;
        if (c < DIM) orow[c] = (v[i] - mean) * rs * w[c] + bb[c];
    }
}

// ---------------------------------------------------------------------------
// Generic tiled GEMM: C[M,N] = A[M,K] @ W[K,N] (+ epilogue)
// BM=BN=128, BK=20, 256 threads, 8x8 per thread, f32x2 FMA.
// EPI: 0=+bias  1=gelu(+bias)  2=window-scatter + residual x  3=+bias+res
// ---------------------------------------------------------------------------
template <int EPI>
__global__ void __launch_bounds__(256)
gemm_kernel(const float* __restrict__ A, const float* __restrict__ Wm,
            const float* __restrict__ bias, float* __restrict__ C,
            const float* __restrict__ res, int M, int N, int K) {
    __shared__ float sA[20][132];   // transposed A tile, padded (row 528B, 16B-aligned)
    __shared__ float sB[20][128];

    int tid = threadIdx.x;
    int tx = tid & 15, ty = tid >> 4;
    int m0 = blockIdx.y << 7, n0 = blockIdx.x << 7;

    unsigned long long acc2[8][4];
#pragma unroll
    for (int i = 0; i < 8; i++)
#pragma unroll
        for (int j = 0; j < 4; j++) acc2[i][j] = 0ull;

    for (int kb = 0; kb < K; kb += 20) {
#pragma unroll
        for (int i = 0; i < 10; i++) {
            int idx = tid + (i << 8);            // 0..2559
            int r = idx / 20, c = idx - r * 20;
            sA[c][r] = A[(size_t)(m0 + r) * K + kb + c];
            int rb = idx >> 7, cb = idx & 127;
            int col = n0 + cb;
            sB[rb][cb] = (col < N) ? Wm[(size_t)(kb + rb) * N + col] : 0.f;
        }
        __syncthreads();
#pragma unroll
        for (int kk = 0; kk < 20; kk++) {
            const float4* pa = reinterpret_cast<const float4*>(&sA[kk][ty << 3]);
            float4 a0 = pa[0], a1 = pa[1];
            const ulonglong2* pb = reinterpret_cast<const ulonglong2*>(&sB[kk][tx << 3]);
            ulonglong2 b0 = pb[0], b1 = pb[1];
            float av[8] = {a0.x, a0.y, a0.z, a0.w, a1.x, a1.y, a1.z, a1.w};
#pragma unroll
            for (int i = 0; i < 8; i++) {
                unsigned long long ap;
                PACK_F32X2(ap, av[i], av[i]);
                FMA_F32X2(acc2[i][0], ap, b0.x, acc2[i][0]);
                FMA_F32X2(acc2[i][1], ap, b0.y, acc2[i][1]);
                FMA_F32X2(acc2[i][2], ap, b1.x, acc2[i][2]);
                FMA_F32X2(acc2[i][3], ap, b1.y, acc2[i][3]);
            }
        }
        __syncthreads();
    }

    // ---- epilogue ----
#pragma unroll
    for (int i = 0; i < 8; i++) {
        int m = m0 + (ty << 3) + i;
        size_t obase;
        if (EPI == 2) {
            // m = b*16384 + win*256 + t  ->  scatter back through reverse shift
            int b  = m >> 14;
            int ri = m & 16383;
            int wi = ri >> 8;
            int t  = ri & 255;
            int hh = (((wi >> 3) << 4) + (t >> 4) + SS) & 127;
            int ww = (((wi & 7) << 4) + (t & 15) + SS) & 127;
            int drow = (b << 14) + (hh << 7) + ww;
            obase = (size_t)drow * DIM;
        } else {
            obase = (size_t)m * N;
        }
#pragma unroll
        for (int jp = 0; jp < 4; jp++) {
            float lo, hi;
            UNPACK_F32X2(lo, hi, acc2[i][jp]);
            float vals[2] = {lo, hi};
            int nbase = n0 + (tx << 3) + (jp << 1);
#pragma unroll
            for (int e = 0; e < 2; e++) {
                int nn = nbase + e;
                if (nn < N) {
                    float v = vals[e] + bias[nn];
                    if (EPI == 1) v = gelu_f(v);
                    if (EPI == 2) v += res[obase + nn];
                    if (EPI == 3) v += res[obase + nn];
                    C[obase + nn] = v;
                }
            }
        }
    }
}

// ---------------------------------------------------------------------------
// Fused shifted-window attention: one block per (window, head), 256 threads.
// Mask computed analytically from coordinates; rel-pos bias table in SMEM.
// Streaming softmax (scores are small; clamped at 60).
// ---------------------------------------------------------------------------
__global__ void __launch_bounds__(256)
attn_kernel(const float* __restrict__ qkv, const float* __restrict__ rpb,
            float* __restrict__ awin) {
    extern __shared__ float smem[];
    float* sk   = smem;                         // 256 * 32
    float* sv   = smem + 8192;                  // 256 * 32
    float* srpb = smem + 16384;                 // 961
    int*   sgrow = (int*)(smem + 16384 + 961);  // 256
    int*   scnt  = sgrow + 256;                 // 256

    int t   = threadIdx.x;
    int wgl = blockIdx.x;       // global window 0..511
    int hid = blockIdx.y;       // head 0..5
    int b  = wgl >> 6, wi = wgl & 63;
    int wy = wi >> 3,  wx = wi & 7;
    int li = t >> 4,   lj = t & 15;

    // rolled gather position (same mapping used for the output scatter)
    int gr = ((wy << 4) + li + SS) & 127;
    int gc = ((wx << 4) + lj + SS) & 127;
    int grow = (b << 14) + (gr << 7) + gc;

    // region id on the UNROLLED grid (Swin mask)
    int ur = (wy << 4) + li, uc = (wx << 4) + lj;
    int rh = (ur < 112) ? 0 : (ur < 120 ? 1 : 2);
    int rc = (uc < 112) ? 0 : (uc < 120 ? 1 : 2);
    int myCnt = rh * 3 + rc;

    sgrow[t] = grow;
    scnt[t]  = myCnt;
    sk[(t << 5) + 30] = 0.f; sk[(t << 5) + 31] = 0.f;
    sv[(t << 5) + 30] = 0.f; sv[(t << 5) + 31] = 0.f;
    for (int idx = t; idx < 961; idx += 256) srpb[idx] = rpb[idx * NHEAD + hid];
    __syncthreads();

    // cooperative, mostly-coalesced K/V fill
    for (int idx = t; idx < 256 * HD; idx += 256) {
        int t2 = idx / HD;
        int d  = idx - t2 * HD;
        int gb = sgrow[t2] * QKVC + hid * HD + d;
        sk[(t2 << 5) + d] = qkv[gb + DIM];
        sv[(t2 << 5) + d] = qkv[gb + 2 * DIM];
    }

    // per-thread query (pre-scaled), packed into f32x2 pairs
    unsigned long long q2[16];
    {
        float qv[32];
        int qb = grow * QKVC + hid * HD;
#pragma unroll
        for (int d = 0; d < HD; d++) qv[d] = qkv[qb + d] * 0.18257418583505536f;
        qv[30] = 0.f; qv[31] = 0.f;
#pragma unroll
        for (int i = 0; i < 16; i++) PACK_F32X2(q2[i], qv[2 * i], qv[2 * i + 1]);
    }
    __syncthreads();

    unsigned long long acc2[16];
#pragma unroll
    for (int i = 0; i < 16; i++) acc2[i] = 0ull;
    float l = 0.f;
    int base_t = (li + 15) * 31 + (lj + 15);

    for (int j = 0; j < 256; j++) {
        const ulonglong2* kp = reinterpret_cast<const ulonglong2*>(sk + (j << 5));
        unsigned long long sa = 0ull, sb = 0ull;
#pragma unroll
        for (int i = 0; i < 8; i++) {
            ulonglong2 kk = kp[i];
            FMA_F32X2(sa, q2[2 * i],     kk.x, sa);
            FMA_F32X2(sb, q2[2 * i + 1], kk.y, sb);
        }
        float a0, a1, b0, b1;
        UNPACK_F32X2(a0, a1, sa);
        UNPACK_F32X2(b0, b1, sb);
        float s = (a0 + b0) + (a1 + b1);

        int off = ((j >> 4) * 31) + (j & 15);
        s += srpb[base_t - off];
        s = (scnt[j] == myCnt) ? s : (s - 100.0f);
        float p = __expf(fminf(s, 60.0f));
        l += p;

        unsigned long long p2;
        PACK_F32X2(p2, p, p);
        const ulonglong2* vp = reinterpret_cast<const ulonglong2*>(sv + (j << 5));
#pragma unroll
        for (int i = 0; i < 8; i++) {
            ulonglong2 vv = vp[i];
            FMA_F32X2(acc2[2 * i],     p2, vv.x, acc2[2 * i]);
            FMA_F32X2(acc2[2 * i + 1], p2, vv.y, acc2[2 * i + 1]);
        }
    }

    float inv = 1.0f / l;
    float* orow = awin + ((size_t)(wgl << 8) + t) * DIM + hid * HD;
#pragma unroll
    for (int i = 0; i < 15; i++) {
        float lo, hi;
        UNPACK_F32X2(lo, hi, acc2[i]);
        orow[2 * i]     = lo * inv;
        orow[2 * i + 1] = hi * inv;
    }
}

// ---------------------------------------------------------------------------
// Depthwise 5x5 conv (channel-last), fused +bias, gelu, +y residual.
// One thread per channel; 8 output columns via register sliding window.
// ---------------------------------------------------------------------------
__global__ void __launch_bounds__(384)
conv_kernel(const float* __restrict__ y, const float* __restrict__ dw,
            const float* __restrict__ db, float* __restrict__ y2) {
    int ch = threadIdx.x;
    if (ch >= HIDDEN) return;
    int c0 = blockIdx.x << 3;
    int r  = blockIdx.y;
    int b  = blockIdx.z;

    float wreg[25];
#pragma unroll
    for (int k = 0; k < 25; k++) wreg[k] = dw[ch * 25 + k];

    float acc[8] = {0, 0, 0, 0, 0, 0, 0, 0};
    float center[8];
    const float* ybase = y + ((size_t)b << 14) * HIDDEN;

#pragma unroll
    for (int ky = 0; ky < 5; ky++) {
        int ry = r + ky - 2;
        bool rv = (ry >= 0) && (ry < HH);
        float v[12];
#pragma unroll
        for (int xx = 0; xx < 12; xx++) {
            int cx = c0 + xx - 2;
            bool cv = rv && (cx >= 0) && (cx < WW2);
            v[xx] = cv ? ybase[((size_t)(ry << 7) + cx) * HIDDEN + ch] : 0.f;
        }
        if (ky == 2) {
#pragma unroll
            for (int o = 0; o < 8; o++) center[o] = v[o + 2];
        }
#pragma unroll
        for (int o = 0; o < 8; o++)
#pragma unroll
            for (int kx = 0; kx < 5; kx++)
                acc[o] = fmaf(v[o + kx], wreg[ky * 5 + kx], acc[o]);
    }

    float bch = db[ch];
#pragma unroll
    for (int o = 0; o < 8; o++) {
        float g = gelu_f(acc[o] + bch);
        y2[(((size_t)b << 14) + (r << 7) + c0 + o) * HIDDEN + ch] = center[o] + g;
    }
}

// ---------------------------------------------------------------------------
// Launch
// ---------------------------------------------------------------------------
#define ATTN_SMEM ((16384 + 961 + 512) * 4)   // 71428 bytes

extern "C" void kernel_launch(void* const* d_in, const int* in_sizes, int n_in,
                              void* d_out, int out_size) {
    const float* x       = (const float*)d_in[0];
    const float* norm1_w = (const float*)d_in[3];
    const float* norm1_b = (const float*)d_in[4];
    const float* wqkv_w  = (const float*)d_in[5];
    const float* wqkv_b  = (const float*)d_in[6];
    const float* rpb     = (const float*)d_in[7];
    const float* proj_w  = (const float*)d_in[8];
    const float* proj_b  = (const float*)d_in[9];
    const float* norm2_w = (const float*)d_in[10];
    const float* norm2_b = (const float*)d_in[11];
    const float* fc1_w   = (const float*)d_in[12];
    const float* fc1_b   = (const float*)d_in[13];
    const float* dw_w    = (const float*)d_in[14];
    const float* dw_b    = (const float*)d_in[15];
    const float* fc2_w   = (const float*)d_in[16];
    const float* fc2_b   = (const float*)d_in[17];
    float* out = (float*)d_out;

    float *ln, *qkv, *awin, *xres, *y, *y2;
    cudaGetSymbolAddress((void**)&ln,   g_ln);
    cudaGetSymbolAddress((void**)&qkv,  g_qkv);
    cudaGetSymbolAddress((void**)&awin, g_awin);
    cudaGetSymbolAddress((void**)&xres, g_xres);
    cudaGetSymbolAddress((void**)&y,    g_y);
    cudaGetSymbolAddress((void**)&y2,   g_y2);

    cudaFuncSetAttribute(attn_kernel,
                         cudaFuncAttributeMaxDynamicSharedMemorySize, ATTN_SMEM);

    const int M = NTOK;

    // 1) LN1
    ln_kernel<<<M / 8, 256>>>(x, norm1_w, norm1_b, ln);
    // 2) QKV GEMM  (M x 180 @ 180 x 540) + bias
    gemm_kernel<0><<<dim3(5, M / 128), 256>>>(ln, wqkv_w, wqkv_b, qkv, nullptr,
                                              M, QKVC, DIM);
    // 3) windowed attention -> awin (window layout)
    attn_kernel<<<dim3(512, NHEAD), 256, ATTN_SMEM>>>(qkv, rpb, awin);
    // 4) proj GEMM + scatter(reverse shift) + residual x -> xres
    gemm_kernel<2><<<dim3(2, M / 128), 256>>>(awin, proj_w, proj_b, xres, x,
                                              M, DIM, DIM);
    // 5) LN2
    ln_kernel<<<M / 8, 256>>>(xres, norm2_w, norm2_b, ln);
    // 6) fc1 GEMM + gelu -> y
    gemm_kernel<1><<<dim3(3, M / 128), 256>>>(ln, fc1_w, fc1_b, y, nullptr,
                                              M, HIDDEN, DIM);
    // 7) depthwise conv + gelu + residual y -> y2
    conv_kernel<<<dim3(16, 128, 8), 384>>>(y, dw_w, dw_b, y2);
    // 8) fc2 GEMM + bias + residual xres -> out
    gemm_kernel<3><<<dim3(2, M / 128), 256>>>(y2, fc2_w, fc2_b, out, xres,
                                              M, DIM, HIDDEN);
}

// round 14
// speedup vs baseline: 1.0015x; 1.0008x over previous
#include <cuda_runtime.h>
#include <math.h>

// ---------------------------------------------------------------------------
// Problem constants
// ---------------------------------------------------------------------------
#define BATCH   8
#define HH      128
#define WW2     128
#define DIM     180
#define NHEAD   6
#define HD      30
#define WS      16
#define SS      8
#define HIDDEN  360
#define NTOK    (BATCH * HH * WW2)          // 131072 rows
#define QKVC    (3 * DIM)                   // 540

// ---------------------------------------------------------------------------
// f32x2 packed math (Blackwell sm_103a)
// ---------------------------------------------------------------------------
#define PACK_F32X2(out, lo, hi) \
    asm("mov.b64 %0, {%1, %2};" : "=l"(out) : "f"(lo), "f"(hi))
#define UNPACK_F32X2(lo, hi, in) \
    asm("mov.b64 {%0, %1}, %2;" : "=f"(lo), "=f"(hi) : "l"(in))
#define FMA_F32X2(d, a, b, c) \
    asm("fma.rn.f32x2 %0, %1, %2, %3;" : "=l"(d) : "l"(a), "l"(b), "l"(c))

__device__ __forceinline__ float gelu_f(float v) {
    return 0.5f * v * (1.0f + erff(v * 0.70710678118654752440f));
}

// ---------------------------------------------------------------------------
// Scratch (device globals — no runtime allocation allowed)
// ---------------------------------------------------------------------------
__device__ float g_ln  [(size_t)NTOK * DIM];     //  94 MB  (LN output, reused)
__device__ float g_qkv [(size_t)NTOK * QKVC];    // 283 MB
__device__ float g_awin[(size_t)NTOK * DIM];     //  94 MB  (attn out, window layout)
__device__ float g_xres[(size_t)NTOK * DIM];     //  94 MB  (x + attn proj)
__device__ float g_y   [(size_t)NTOK * HIDDEN];  // 189 MB  (gelu(fc1))
__device__ float g_y2  [(size_t)NTOK * HIDDEN];  // 189 MB  (y + gelu(dwconv))

// ---------------------------------------------------------------------------
// LayerNorm: one warp per row of 180
// ---------------------------------------------------------------------------
__global__ void __launch_bounds__(256)
ln_kernel(const float* __restrict__ x, const float* __restrict__ w,
          const float* __restrict__ bb, float* __restrict__ out) {
    int lane = threadIdx.x & 31;
    int row  = blockIdx.x * 8 + (threadIdx.x >> 5);
    const float* xr = x + (size_t)row * DIM;

    float v[6];
    float s = 0.f;
#pragma unroll
    for (int i = 0; i < 6; i++) {
        int c = lane + i * 32;
        v[i] = (c < DIM) ? xr[c] : 0.f;
        s += v[i];
    }
#pragma unroll
    for (int o = 16; o; o >>= 1) s += __shfl_xor_sync(0xffffffffu, s, o);
    float mean = s * (1.0f / DIM);

    float vs = 0.f;
#pragma unroll
    for (int i = 0; i < 6; i++) {
        int c = lane + i * 32;
        if (c < DIM) { float d = v[i] - mean; vs += d * d; }
    }
#pragma unroll
    for (int o = 16; o; o >>= 1) vs += __shfl_xor_sync(0xffffffffu, vs, o);
    float rs = rsqrtf(vs * (1.0f / DIM) + 1e-5f);

    float* orow = out + (size_t)row * DIM;
#pragma unroll
    for (int i = 0; i < 6; i++) {
        int c = lane + i * 32;
        if (c < DIM) orow[c] = (v[i] - mean) * rs * w[c] + bb[c];
    }
}

// ---------------------------------------------------------------------------
// Generic tiled GEMM: C[M,N] = A[M,K] @ W[K,N] (+ epilogue)
// BM=BN=128, BK=20, 256 threads, 8x8 per thread, f32x2 FMA.
// EPI: 0=+bias  1=gelu(+bias)  2=window-scatter + residual x  3=+bias+res
// ---------------------------------------------------------------------------
template <int EPI>
__global__ void __launch_bounds__(256)
gemm_kernel(const float* __restrict__ A, const float* __restrict__ Wm,
            const float* __restrict__ bias, float* __restrict__ C,
            const float* __restrict__ res, int M, int N, int K) {
    __shared__ float sA[20][132];   // transposed A tile, padded (row 528B, 16B-aligned)
    __shared__ float sB[20][128];

    int tid = threadIdx.x;
    int tx = tid & 15, ty = tid >> 4;
    int m0 = blockIdx.y << 7, n0 = blockIdx.x << 7;

    unsigned long long acc2[8][4];
#pragma unroll
    for (int i = 0; i < 8; i++)
#pragma unroll
        for (int j = 0; j < 4; j++) acc2[i][j] = 0ull;

    for (int kb = 0; kb < K; kb += 20) {
#pragma unroll
        for (int i = 0; i < 10; i++) {
            int idx = tid + (i << 8);            // 0..2559
            int r = idx / 20, c = idx - r * 20;
            sA[c][r] = A[(size_t)(m0 + r) * K + kb + c];
            int rb = idx >> 7, cb = idx & 127;
            int col = n0 + cb;
            sB[rb][cb] = (col < N) ? Wm[(size_t)(kb + rb) * N + col] : 0.f;
        }
        __syncthreads();
#pragma unroll
        for (int kk = 0; kk < 20; kk++) {
            const float4* pa = reinterpret_cast<const float4*>(&sA[kk][ty << 3]);
            float4 a0 = pa[0], a1 = pa[1];
            const ulonglong2* pb = reinterpret_cast<const ulonglong2*>(&sB[kk][tx << 3]);
            ulonglong2 b0 = pb[0], b1 = pb[1];
            float av[8] = {a0.x, a0.y, a0.z, a0.w, a1.x, a1.y, a1.z, a1.w};
#pragma unroll
            for (int i = 0; i < 8; i++) {
                unsigned long long ap;
                PACK_F32X2(ap, av[i], av[i]);
                FMA_F32X2(acc2[i][0], ap, b0.x, acc2[i][0]);
                FMA_F32X2(acc2[i][1], ap, b0.y, acc2[i][1]);
                FMA_F32X2(acc2[i][2], ap, b1.x, acc2[i][2]);
                FMA_F32X2(acc2[i][3], ap, b1.y, acc2[i][3]);
            }
        }
        __syncthreads();
    }

    // ---- epilogue ----
#pragma unroll
    for (int i = 0; i < 8; i++) {
        int m = m0 + (ty << 3) + i;
        size_t obase;
        if (EPI == 2) {
            // m = b*16384 + win*256 + t  ->  scatter back through reverse shift
            int b  = m >> 14;
            int ri = m & 16383;
            int wi = ri >> 8;
            int t  = ri & 255;
            int hh = (((wi >> 3) << 4) + (t >> 4) + SS) & 127;
            int ww = (((wi & 7) << 4) + (t & 15) + SS) & 127;
            int drow = (b << 14) + (hh << 7) + ww;
            obase = (size_t)drow * DIM;
        } else {
            obase = (size_t)m * N;
        }
#pragma unroll
        for (int jp = 0; jp < 4; jp++) {
            float lo, hi;
            UNPACK_F32X2(lo, hi, acc2[i][jp]);
            float vals[2] = {lo, hi};
            int nbase = n0 + (tx << 3) + (jp << 1);
#pragma unroll
            for (int e = 0; e < 2; e++) {
                int nn = nbase + e;
                if (nn < N) {
                    float v = vals[e] + bias[nn];
                    if (EPI == 1) v = gelu_f(v);
                    if (EPI == 2) v += res[obase + nn];
                    if (EPI == 3) v += res[obase + nn];
                    C[obase + nn] = v;
                }
            }
        }
    }
}

// ---------------------------------------------------------------------------
// Fused shifted-window attention: one block per (window, head), 256 threads.
// Mask computed analytically from coordinates; rel-pos bias table in SMEM.
// Streaming softmax (scores are small; clamped at 60).
// ---------------------------------------------------------------------------
__global__ void __launch_bounds__(256)
attn_kernel(const float* __restrict__ qkv, const float* __restrict__ rpb,
            float* __restrict__ awin) {
    extern __shared__ float smem[];
    float* sk   = smem;                         // 256 * 32
    float* sv   = smem + 8192;                  // 256 * 32
    float* srpb = smem + 16384;                 // 961
    int*   sgrow = (int*)(smem + 16384 + 961);  // 256
    int*   scnt  = sgrow + 256;                 // 256

    int t   = threadIdx.x;
    int wgl = blockIdx.x;       // global window 0..511
    int hid = blockIdx.y;       // head 0..5
    int b  = wgl >> 6, wi = wgl & 63;
    int wy = wi >> 3,  wx = wi & 7;
    int li = t >> 4,   lj = t & 15;

    // rolled gather position (same mapping used for the output scatter)
    int gr = ((wy << 4) + li + SS) & 127;
    int gc = ((wx << 4) + lj + SS) & 127;
    int grow = (b << 14) + (gr << 7) + gc;

    // region id on the UNROLLED grid (Swin mask)
    int ur = (wy << 4) + li, uc = (wx << 4) + lj;
    int rh = (ur < 112) ? 0 : (ur < 120 ? 1 : 2);
    int rc = (uc < 112) ? 0 : (uc < 120 ? 1 : 2);
    int myCnt = rh * 3 + rc;

    sgrow[t] = grow;
    scnt[t]  = myCnt;
    sk[(t << 5) + 30] = 0.f; sk[(t << 5) + 31] = 0.f;
    sv[(t << 5) + 30] = 0.f; sv[(t << 5) + 31] = 0.f;
    for (int idx = t; idx < 961; idx += 256) srpb[idx] = rpb[idx * NHEAD + hid];
    __syncthreads();

    // cooperative, mostly-coalesced K/V fill
    for (int idx = t; idx < 256 * HD; idx += 256) {
        int t2 = idx / HD;
        int d  = idx - t2 * HD;
        int gb = sgrow[t2] * QKVC + hid * HD + d;
        sk[(t2 << 5) + d] = qkv[gb + DIM];
        sv[(t2 << 5) + d] = qkv[gb + 2 * DIM];
    }

    // per-thread query (pre-scaled), packed into f32x2 pairs
    unsigned long long q2[16];
    {
        float qv[32];
        int qb = grow * QKVC + hid * HD;
#pragma unroll
        for (int d = 0; d < HD; d++) qv[d] = qkv[qb + d] * 0.18257418583505536f;
        qv[30] = 0.f; qv[31] = 0.f;
#pragma unroll
        for (int i = 0; i < 16; i++) PACK_F32X2(q2[i], qv[2 * i], qv[2 * i + 1]);
    }
    __syncthreads();

    unsigned long long acc2[16];
#pragma unroll
    for (int i = 0; i < 16; i++) acc2[i] = 0ull;
    float l = 0.f;
    int base_t = (li + 15) * 31 + (lj + 15);

    for (int j = 0; j < 256; j++) {
        const ulonglong2* kp = reinterpret_cast<const ulonglong2*>(sk + (j << 5));
        unsigned long long sa = 0ull, sb = 0ull;
#pragma unroll
        for (int i = 0; i < 8; i++) {
            ulonglong2 kk = kp[i];
            FMA_F32X2(sa, q2[2 * i],     kk.x, sa);
            FMA_F32X2(sb, q2[2 * i + 1], kk.y, sb);
        }
        float a0, a1, b0, b1;
        UNPACK_F32X2(a0, a1, sa);
        UNPACK_F32X2(b0, b1, sb);
        float s = (a0 + b0) + (a1 + b1);

        int off = ((j >> 4) * 31) + (j & 15);
        s += srpb[base_t - off];
        s = (scnt[j] == myCnt) ? s : (s - 100.0f);
        float p = __expf(fminf(s, 60.0f));
        l += p;

        unsigned long long p2;
        PACK_F32X2(p2, p, p);
        const ulonglong2* vp = reinterpret_cast<const ulonglong2*>(sv + (j << 5));
#pragma unroll
        for (int i = 0; i < 8; i++) {
            ulonglong2 vv = vp[i];
            FMA_F32X2(acc2[2 * i],     p2, vv.x, acc2[2 * i]);
            FMA_F32X2(acc2[2 * i + 1], p2, vv.y, acc2[2 * i + 1]);
        }
    }

    float inv = 1.0f / l;
    float* orow = awin + ((size_t)(wgl << 8) + t) * DIM + hid * HD;
#pragma unroll
    for (int i = 0; i < 15; i++) {
        float lo, hi;
        UNPACK_F32X2(lo, hi, acc2[i]);
        orow[2 * i]     = lo * inv;
        orow[2 * i + 1] = hi * inv;
    }
}

// ---------------------------------------------------------------------------
// Depthwise 5x5 conv (channel-last), fused +bias, gelu, +y residual.
// One thread per channel; 8 output columns via register sliding window.
// ---------------------------------------------------------------------------
__global__ void __launch_bounds__(384)
conv_kernel(const float* __restrict__ y, const float* __restrict__ dw,
            const float* __restrict__ db, float* __restrict__ y2) {
    int ch = threadIdx.x;
    if (ch >= HIDDEN) return;
    int c0 = blockIdx.x << 3;
    int r  = blockIdx.y;
    int b  = blockIdx.z;

    float wreg[25];
#pragma unroll
    for (int k = 0; k < 25; k++) wreg[k] = dw[ch * 25 + k];

    float acc[8] = {0, 0, 0, 0, 0, 0, 0, 0};
    float center[8];
    const float* ybase = y + ((size_t)b << 14) * HIDDEN;

#pragma unroll
    for (int ky = 0; ky < 5; ky++) {
        int ry = r + ky - 2;
        bool rv = (ry >= 0) && (ry < HH);
        float v[12];
#pragma unroll
        for (int xx = 0; xx < 12; xx++) {
            int cx = c0 + xx - 2;
            bool cv = rv && (cx >= 0) && (cx < WW2);
            v[xx] = cv ? ybase[((size_t)(ry << 7) + cx) * HIDDEN + ch] : 0.f;
        }
        if (ky == 2) {
#pragma unroll
            for (int o = 0; o < 8; o++) center[o] = v[o + 2];
        }
#pragma unroll
        for (int o = 0; o < 8; o++)
#pragma unroll
            for (int kx = 0; kx < 5; kx++)
                acc[o] = fmaf(v[o + kx], wreg[ky * 5 + kx], acc[o]);
    }

    float bch = db[ch];
#pragma unroll
    for (int o = 0; o < 8; o++) {
        float g = gelu_f(acc[o] + bch);
        y2[(((size_t)b << 14) + (r << 7) + c0 + o) * HIDDEN + ch] = center[o] + g;
    }
}

// ---------------------------------------------------------------------------
// Launch
// ---------------------------------------------------------------------------
#define ATTN_SMEM ((16384 + 961 + 512) * 4)   // 71428 bytes

extern "C" void kernel_launch(void* const* d_in, const int* in_sizes, int n_in,
                              void* d_out, int out_size) {
    const float* x       = (const float*)d_in[0];
    const float* norm1_w = (const float*)d_in[3];
    const float* norm1_b = (const float*)d_in[4];
    const float* wqkv_w  = (const float*)d_in[5];
    const float* wqkv_b  = (const float*)d_in[6];
    const float* rpb     = (const float*)d_in[7];
    const float* proj_w  = (const float*)d_in[8];
    const float* proj_b  = (const float*)d_in[9];
    const float* norm2_w = (const float*)d_in[10];
    const float* norm2_b = (const float*)d_in[11];
    const float* fc1_w   = (const float*)d_in[12];
    const float* fc1_b   = (const float*)d_in[13];
    const float* dw_w    = (const float*)d_in[14];
    const float* dw_b    = (const float*)d_in[15];
    const float* fc2_w   = (const float*)d_in[16];
    const float* fc2_b   = (const float*)d_in[17];
    float* out = (float*)d_out;

    float *ln, *qkv, *awin, *xres, *y, *y2;
    cudaGetSymbolAddress((void**)&ln,   g_ln);
    cudaGetSymbolAddress((void**)&qkv,  g_qkv);
    cudaGetSymbolAddress((void**)&awin, g_awin);
    cudaGetSymbolAddress((void**)&xres, g_xres);
    cudaGetSymbolAddress((void**)&y,    g_y);
    cudaGetSymbolAddress((void**)&y2,   g_y2);

    cudaFuncSetAttribute(attn_kernel,
                         cudaFuncAttributeMaxDynamicSharedMemorySize, ATTN_SMEM);

    const int M = NTOK;

    // 1) LN1
    ln_kernel<<<M / 8, 256>>>(x, norm1_w, norm1_b, ln);
    // 2) QKV GEMM  (M x 180 @ 180 x 540) + bias
    gemm_kernel<0><<<dim3(5, M / 128), 256>>>(ln, wqkv_w, wqkv_b, qkv, nullptr,
                                              M, QKVC, DIM);
    // 3) windowed attention -> awin (window layout)
    attn_kernel<<<dim3(512, NHEAD), 256, ATTN_SMEM>>>(qkv, rpb, awin);
    // 4) proj GEMM + scatter(reverse shift) + residual x -> xres
    gemm_kernel<2><<<dim3(2, M / 128), 256>>>(awin, proj_w, proj_b, xres, x,
                                              M, DIM, DIM);
    // 5) LN2
    ln_kernel<<<M / 8, 256>>>(xres, norm2_w, norm2_b, ln);
    // 6) fc1 GEMM + gelu -> y
    gemm_kernel<1><<<dim3(3, M / 128), 256>>>(ln, fc1_w, fc1_b, y, nullptr,
                                              M, HIDDEN, DIM);
    // 7) depthwise conv + gelu + residual y -> y2
    conv_kernel<<<dim3(16, 128, 8), 384>>>(y, dw_w, dw_b, y2);
    // 8) fc2 GEMM + bias + residual xres -> out
    gemm_kernel<3><<<dim3(2, M / 128), 256>>>(y2, fc2_w, fc2_b, out, xres,
                                              M, DIM, HIDDEN);
}